// round 10
// baseline (speedup 1.0000x reference)
#include <cuda_runtime.h>
#include <cuda_bf16.h>
#include <cstdint>

#define BATCH 4
#define CDIM  512
#define NPIX  4096
#define ODIM  64

typedef __nv_bfloat16 bf16;

// ---------------- scratch (device globals; runtime alloc forbidden) --------
__device__ __align__(16) bf16  g_xt [BATCH * NPIX * CDIM];          // x^T bf16 [b][n][c] (16.8 MB)
__device__ __align__(16) bf16  g_wfg[128 * CDIM];                   // stacked f_w,g_w bf16
__device__ __align__(16) float g_bfg[128];                          // stacked f_b,g_b
__device__ __align__(16) bf16  g_wh [CDIM * CDIM];                  // h_w bf16
__device__ __align__(16) bf16  g_fg [BATCH * NPIX * 128];           // fgT[b][n][o]: f cols 0..63, g cols 64..127
__device__ __align__(16) bf16  g_hv [BATCH * CDIM * NPIX];          // h projection bf16 [b][c][n]
__device__ __align__(16) bf16  g_pb [(size_t)BATCH * NPIX * NPIX];  // scores^T -> probs, bf16 in place (134 MB)

// ---------------- weight pack -----------------------------------------------
__global__ void pack_kernel(const float* __restrict__ fw, const float* __restrict__ fb,
                            const float* __restrict__ gw, const float* __restrict__ gb,
                            const float* __restrict__ hw)
{
    int i = blockIdx.x * 256 + threadIdx.x;           // grid covers CDIM*CDIM
    if (i < 128 * CDIM)
        g_wfg[i] = __float2bfloat16(i < 64 * CDIM ? fw[i] : gw[i - 64 * CDIM]);
    if (i < CDIM * CDIM)
        g_wh[i] = __float2bfloat16(hw[i]);
    if (i < 128)
        g_bfg[i] = (i < 64) ? fb[i] : gb[i - 64];
}

// ---------------- x transpose: [b][c][n] fp32 -> [b][n][c] bf16 -------------
// Tile: 64 c x 32 n. Block (32, 8).
__global__ __launch_bounds__(256) void transpose_x(const float* __restrict__ x)
{
    __shared__ float t[64][33];
    int b  = blockIdx.z;
    int c0 = blockIdx.y * 64;
    int n0 = blockIdx.x * 32;
    const float* xb = x + (size_t)b * CDIM * NPIX;
    bf16* xo = g_xt + (size_t)b * NPIX * CDIM;
    int tx = threadIdx.x, ty = threadIdx.y;

    #pragma unroll
    for (int e = 0; e < 8; e++) {
        int c = 8 * e + ty;          // 0..63
        t[c][tx] = xb[(size_t)(c0 + c) * NPIX + n0 + tx];
    }
    __syncthreads();
    #pragma unroll
    for (int e = 0; e < 4; e++) {
        int n = ty + 8 * e;          // 0..31
        __nv_bfloat162 v = __float22bfloat162_rn(
            make_float2(t[2 * tx][n], t[2 * tx + 1][n]));
        *(__nv_bfloat162*)(xo + (size_t)(n0 + n) * CDIM + c0 + 2 * tx) = v;
    }
}

// ---------------- mma helper ------------------------------------------------
__device__ __forceinline__ void mma16816(float* d, const uint32_t* a, const uint32_t* b)
{
    asm volatile(
        "mma.sync.aligned.m16n8k16.row.col.f32.bf16.bf16.f32 "
        "{%0,%1,%2,%3}, {%4,%5,%6,%7}, {%8,%9}, {%0,%1,%2,%3};"
        : "+f"(d[0]), "+f"(d[1]), "+f"(d[2]), "+f"(d[3])
        : "r"(a[0]), "r"(a[1]), "r"(a[2]), "r"(a[3]), "r"(b[0]), "r"(b[1]));
}

// ---------------- tile staging (K-contiguous rows only) --------------------
// 128 rows x 32 k halfs per operand tile; 2 uint4 per thread.
__device__ __forceinline__ void load_tile_regs(uint4* r, const bf16* src, int ld, int tid)
{
    #pragma unroll
    for (int e = 0; e < 2; e++) {
        int c = tid + 256 * e;
        int rr = c >> 2, q = c & 3;
        r[e] = *(const uint4*)(src + (size_t)rr * ld + 8 * q);
    }
}
__device__ __forceinline__ void store_tile_regs(bf16* sm, const uint4* r, int tid)
{
    #pragma unroll
    for (int e = 0; e < 2; e++) {
        int c = tid + 256 * e;
        int rr = c >> 2, q = c & 3;
        *(uint4*)(sm + rr * 40 + 8 * q) = r[e];   // row stride 40: conflict-free
    }
}

// ---------------- unified bf16 GEMM (double-buffered) ----------------------
// C[m,n] = sum_k A[m,k] * B[n,k]  (fp32 accum). Block 128x128, warp 64x32, Ktile 32.
// EPI: 0 = +bias[row] -> bf16 ; 1 = plain bf16 store ; 2 = gamma*acc + Xres -> fp32 ;
//      3 = +bias[col] -> bf16
template<int EPI>
__global__ __launch_bounds__(256, 2) void gemm_kernel(
    const bf16* __restrict__ A, size_t strideA, int ldA,
    const bf16* __restrict__ B, size_t strideB, int ldB,
    void* __restrict__ Cv, size_t strideC, int ldC,
    const float* __restrict__ bias,
    const float* __restrict__ Xres, const float* __restrict__ gammap,
    int K)
{
    __shared__ __align__(16) bf16 As[2][128 * 40];
    __shared__ __align__(16) bf16 Bs[2][128 * 40];

    int tid = threadIdx.x;
    int b   = blockIdx.z;
    int m0  = blockIdx.y * 128, n0 = blockIdx.x * 128;
    const bf16* Ab = A + strideA * b + (size_t)m0 * ldA;
    const bf16* Bb = B + strideB * b + (size_t)n0 * ldB;

    int w = tid >> 5, lane = tid & 31;
    int wm = w >> 2, wn = w & 3;          // 2 x 4 warps
    int g  = lane >> 2, tig = lane & 3;

    float acc[4][4][4] = {};

    // prologue: tile 0 -> smem buffer 0
    uint4 ra[2], rb[2];
    load_tile_regs(ra, Ab, ldA, tid);
    load_tile_regs(rb, Bb, ldB, tid);
    store_tile_regs(As[0], ra, tid);
    store_tile_regs(Bs[0], rb, tid);
    __syncthreads();

    int ntiles = K >> 5;
    int cur = 0;
    for (int kt = 0; kt < ntiles; kt++) {
        // prefetch next tile into registers (overlaps with MMAs below)
        if (kt + 1 < ntiles) {
            load_tile_regs(ra, Ab + ((kt + 1) << 5), ldA, tid);
            load_tile_regs(rb, Bb + ((kt + 1) << 5), ldB, tid);
        }

        const bf16* Asc = As[cur];
        const bf16* Bsc = Bs[cur];
        #pragma unroll
        for (int ks = 0; ks < 2; ks++) {
            int kb = ks * 16;
            uint32_t af[4][4], bfr[4][2];
            #pragma unroll
            for (int mf = 0; mf < 4; mf++) {
                const bf16* ap = Asc + (wm * 64 + mf * 16 + g) * 40 + kb + 2 * tig;
                af[mf][0] = *(const uint32_t*)ap;
                af[mf][1] = *(const uint32_t*)(ap + 8 * 40);
                af[mf][2] = *(const uint32_t*)(ap + 8);
                af[mf][3] = *(const uint32_t*)(ap + 8 * 40 + 8);
            }
            #pragma unroll
            for (int nf = 0; nf < 4; nf++) {
                const bf16* bp = Bsc + (wn * 32 + nf * 8 + g) * 40 + kb + 2 * tig;
                bfr[nf][0] = *(const uint32_t*)bp;
                bfr[nf][1] = *(const uint32_t*)(bp + 8);
            }
            #pragma unroll
            for (int mf = 0; mf < 4; mf++)
                #pragma unroll
                for (int nf = 0; nf < 4; nf++)
                    mma16816(acc[mf][nf], af[mf], bfr[nf]);
        }

        if (kt + 1 < ntiles) {
            // buffer cur^1's readers were fenced by the previous iteration's sync
            store_tile_regs(As[cur ^ 1], ra, tid);
            store_tile_regs(Bs[cur ^ 1], rb, tid);
            __syncthreads();
            cur ^= 1;
        }
    }

    float gv = (EPI == 2) ? *gammap : 0.f;

    #pragma unroll
    for (int mf = 0; mf < 4; mf++) {
        #pragma unroll
        for (int rr = 0; rr < 2; rr++) {
            int row = m0 + wm * 64 + mf * 16 + rr * 8 + g;
            #pragma unroll
            for (int nf = 0; nf < 4; nf++) {
                int col = n0 + wn * 32 + nf * 8 + 2 * tig;
                float d0 = acc[mf][nf][rr * 2 + 0];
                float d1 = acc[mf][nf][rr * 2 + 1];
                size_t idx = strideC * b + (size_t)row * ldC + col;
                if (EPI == 0) {
                    float bv = bias[row];
                    *(__nv_bfloat162*)((bf16*)Cv + idx) =
                        __float22bfloat162_rn(make_float2(d0 + bv, d1 + bv));
                } else if (EPI == 1) {
                    *(__nv_bfloat162*)((bf16*)Cv + idx) =
                        __float22bfloat162_rn(make_float2(d0, d1));
                } else if (EPI == 2) {
                    float2 xv = *(const float2*)(Xres + idx);
                    *(float2*)((float*)Cv + idx) =
                        make_float2(gv * d0 + xv.x, gv * d1 + xv.y);
                } else {
                    *(__nv_bfloat162*)((bf16*)Cv + idx) =
                        __float22bfloat162_rn(make_float2(d0 + bias[col], d1 + bias[col + 1]));
                }
            }
        }
    }
}

// ---------------- row softmax, in place on g_pb (bf16), 16B vectorized -----
__global__ __launch_bounds__(256) void softmax_kernel()
{
    __shared__ float red[8];
    size_t row = blockIdx.x;
    bf16* r = g_pb + row * (size_t)NPIX;
    int tid = threadIdx.x;

    // load 2 x uint4 = 16 bf16 per thread (256 threads x 16 = 4096)
    uint4 pk[2];
    float v[16];
    float lmax = -1e30f;
    #pragma unroll
    for (int e = 0; e < 2; e++) {
        pk[e] = *(const uint4*)(r + 8 * (tid + 256 * e));
        const __nv_bfloat162* h2 = (const __nv_bfloat162*)&pk[e];
        #pragma unroll
        for (int q = 0; q < 4; q++) {
            float2 f2 = __bfloat1622float2(h2[q]);
            v[8 * e + 2 * q]     = f2.x;
            v[8 * e + 2 * q + 1] = f2.y;
            lmax = fmaxf(lmax, fmaxf(f2.x, f2.y));
        }
    }
    #pragma unroll
    for (int off = 16; off > 0; off >>= 1)
        lmax = fmaxf(lmax, __shfl_xor_sync(0xffffffffu, lmax, off));
    if ((tid & 31) == 0) red[tid >> 5] = lmax;
    __syncthreads();
    float m = red[0];
    #pragma unroll
    for (int i = 1; i < 8; i++) m = fmaxf(m, red[i]);
    __syncthreads();

    float lsum = 0.f;
    #pragma unroll
    for (int e = 0; e < 16; e++) {
        v[e] = __expf(v[e] - m);
        lsum += v[e];
    }
    #pragma unroll
    for (int off = 16; off > 0; off >>= 1)
        lsum += __shfl_xor_sync(0xffffffffu, lsum, off);
    if ((tid & 31) == 0) red[tid >> 5] = lsum;
    __syncthreads();
    float s = 0.f;
    #pragma unroll
    for (int i = 0; i < 8; i++) s += red[i];
    float inv = 1.0f / s;

    #pragma unroll
    for (int e = 0; e < 2; e++) {
        __nv_bfloat162* h2 = (__nv_bfloat162*)&pk[e];
        #pragma unroll
        for (int q = 0; q < 4; q++)
            h2[q] = __float22bfloat162_rn(
                make_float2(v[8 * e + 2 * q] * inv, v[8 * e + 2 * q + 1] * inv));
        *(uint4*)(r + 8 * (tid + 256 * e)) = pk[e];
    }
}

// ---------------------------------------------------------------------------
extern "C" void kernel_launch(void* const* d_in, const int* in_sizes, int n_in,
                              void* d_out, int out_size)
{
    const float* x     = (const float*)d_in[0];
    const float* f_w   = (const float*)d_in[1];
    const float* f_b   = (const float*)d_in[2];
    const float* g_w   = (const float*)d_in[3];
    const float* g_b   = (const float*)d_in[4];
    const float* h_w   = (const float*)d_in[5];
    const float* h_b   = (const float*)d_in[6];
    const float* gamma = (const float*)d_in[7];
    float* out = (float*)d_out;

    bf16 *xt, *wfg, *wh, *fg, *hv, *pb;
    float *bfg;
    cudaGetSymbolAddress((void**)&xt,  g_xt);
    cudaGetSymbolAddress((void**)&wfg, g_wfg);
    cudaGetSymbolAddress((void**)&wh,  g_wh);
    cudaGetSymbolAddress((void**)&fg,  g_fg);
    cudaGetSymbolAddress((void**)&hv,  g_hv);
    cudaGetSymbolAddress((void**)&pb,  g_pb);
    cudaGetSymbolAddress((void**)&bfg, g_bfg);

    // 0) weights -> bf16; x -> x^T bf16
    pack_kernel<<<(CDIM * CDIM) / 256, 256>>>(f_w, f_b, g_w, g_b, h_w);
    transpose_x<<<dim3(NPIX / 32, CDIM / 64, BATCH), dim3(32, 8)>>>(x);

    // 1) fgT[n, o] = sum_c xT[n,c] * wfg[o,c] + bias[o]   (M=4096, N=128, K=512) -> bf16
    gemm_kernel<3><<<dim3(1, NPIX / 128, BATCH), 256>>>(
        xt, (size_t)NPIX * CDIM, CDIM,
        wfg, 0, CDIM,
        fg, (size_t)NPIX * 128, 128,
        bfg, nullptr, nullptr, CDIM);

    // 2) h[c, n] = sum_k h_w[c,k] * xT[n,k] + h_b[c]      (M=512, N=4096, K=512) -> bf16
    gemm_kernel<0><<<dim3(NPIX / 128, CDIM / 128, BATCH), 256>>>(
        wh, 0, CDIM,
        xt, (size_t)NPIX * CDIM, CDIM,
        hv, (size_t)CDIM * NPIX, NPIX,
        h_b, nullptr, nullptr, CDIM);

    // 3) P[j, i] = sum_o gT[j,o] * fT[i,o]                (M=N=4096, K=64) -> bf16
    gemm_kernel<1><<<dim3(NPIX / 128, NPIX / 128, BATCH), 256>>>(
        fg + 64, (size_t)NPIX * 128, 128,
        fg,      (size_t)NPIX * 128, 128,
        pb, (size_t)NPIX * NPIX, NPIX,
        nullptr, nullptr, nullptr, ODIM);

    // 4) in-place row softmax over P rows (== softmax over dim=1 of original scores)
    softmax_kernel<<<BATCH * NPIX, 256>>>();

    // 5) out[c,m] = gamma * sum_n h[c,n] * Pb[m,n] + x[c,m]  (K=4096) -> fp32
    gemm_kernel<2><<<dim3(NPIX / 128, CDIM / 128, BATCH), 256>>>(
        hv, (size_t)CDIM * NPIX, NPIX,
        pb, (size_t)NPIX * NPIX, NPIX,
        out, (size_t)CDIM * NPIX, NPIX,
        nullptr, x, gamma, NPIX);
}

// round 11
// speedup vs baseline: 1.0808x; 1.0808x over previous
#include <cuda_runtime.h>
#include <cuda_bf16.h>
#include <cstdint>

#define BATCH 4
#define CDIM  512
#define NPIX  4096
#define ODIM  64

typedef __nv_bfloat16 bf16;

// ---------------- scratch (device globals; runtime alloc forbidden) --------
__device__ __align__(16) bf16  g_xt [BATCH * NPIX * CDIM];          // x^T bf16 [b][n][c] (16.8 MB)
__device__ __align__(16) bf16  g_wfg[128 * CDIM];                   // stacked f_w,g_w bf16
__device__ __align__(16) float g_bfg[128];                          // stacked f_b,g_b
__device__ __align__(16) bf16  g_wh [CDIM * CDIM];                  // h_w bf16
__device__ __align__(16) bf16  g_fg [BATCH * NPIX * 128];           // fgT[b][n][o]: f cols 0..63, g cols 64..127
__device__ __align__(16) bf16  g_hv [BATCH * CDIM * NPIX];          // h projection bf16 [b][c][n]
__device__ __align__(16) bf16  g_pb [(size_t)BATCH * NPIX * NPIX];  // scores^T -> probs, bf16 in place (134 MB)

// ---------------- weight pack -----------------------------------------------
__global__ void pack_kernel(const float* __restrict__ fw, const float* __restrict__ fb,
                            const float* __restrict__ gw, const float* __restrict__ gb,
                            const float* __restrict__ hw)
{
    int i = blockIdx.x * 256 + threadIdx.x;           // grid covers CDIM*CDIM
    if (i < 128 * CDIM)
        g_wfg[i] = __float2bfloat16(i < 64 * CDIM ? fw[i] : gw[i - 64 * CDIM]);
    if (i < CDIM * CDIM)
        g_wh[i] = __float2bfloat16(hw[i]);
    if (i < 128)
        g_bfg[i] = (i < 64) ? fb[i] : gb[i - 64];
}

// ---------------- x transpose: [b][c][n] fp32 -> [b][n][c] bf16 -------------
__global__ __launch_bounds__(256) void transpose_x(const float* __restrict__ x)
{
    __shared__ float t[64][33];
    int b  = blockIdx.z;
    int c0 = blockIdx.y * 64;
    int n0 = blockIdx.x * 32;
    const float* xb = x + (size_t)b * CDIM * NPIX;
    bf16* xo = g_xt + (size_t)b * NPIX * CDIM;
    int tx = threadIdx.x, ty = threadIdx.y;

    #pragma unroll
    for (int e = 0; e < 8; e++) {
        int c = 8 * e + ty;
        t[c][tx] = xb[(size_t)(c0 + c) * NPIX + n0 + tx];
    }
    __syncthreads();
    #pragma unroll
    for (int e = 0; e < 4; e++) {
        int n = ty + 8 * e;
        __nv_bfloat162 v = __float22bfloat162_rn(
            make_float2(t[2 * tx][n], t[2 * tx + 1][n]));
        *(__nv_bfloat162*)(xo + (size_t)(n0 + n) * CDIM + c0 + 2 * tx) = v;
    }
}

// ---------------- mma / ldmatrix helpers ------------------------------------
__device__ __forceinline__ void mma16816(float* d, const uint32_t* a, const uint32_t* b)
{
    asm volatile(
        "mma.sync.aligned.m16n8k16.row.col.f32.bf16.bf16.f32 "
        "{%0,%1,%2,%3}, {%4,%5,%6,%7}, {%8,%9}, {%0,%1,%2,%3};"
        : "+f"(d[0]), "+f"(d[1]), "+f"(d[2]), "+f"(d[3])
        : "r"(a[0]), "r"(a[1]), "r"(a[2]), "r"(a[3]), "r"(b[0]), "r"(b[1]));
}

__device__ __forceinline__ void ldsm_x4(uint32_t* r, uint32_t saddr)
{
    asm volatile("ldmatrix.sync.aligned.m8n8.x4.shared.b16 {%0,%1,%2,%3}, [%4];"
        : "=r"(r[0]), "=r"(r[1]), "=r"(r[2]), "=r"(r[3]) : "r"(saddr));
}

// ---------------- tile staging (K-contiguous rows only) --------------------
// 128 rows x 32 k halfs per operand tile; 2 uint4 per thread. Row stride 40.
__device__ __forceinline__ void load_tile_regs(uint4* r, const bf16* src, int ld, int tid)
{
    #pragma unroll
    for (int e = 0; e < 2; e++) {
        int c = tid + 256 * e;
        int rr = c >> 2, q = c & 3;
        r[e] = *(const uint4*)(src + (size_t)rr * ld + 8 * q);
    }
}
__device__ __forceinline__ void store_tile_regs(bf16* sm, const uint4* r, int tid)
{
    #pragma unroll
    for (int e = 0; e < 2; e++) {
        int c = tid + 256 * e;
        int rr = c >> 2, q = c & 3;
        *(uint4*)(sm + rr * 40 + 8 * q) = r[e];
    }
}

// ---------------- unified bf16 GEMM (double-buffered, LDSM frags) ----------
// C[m,n] = sum_k A[m,k] * B[n,k]  (fp32 accum). Block 128x128, warp 64x32, Ktile 32.
// EPI: 0 = +bias[row] -> bf16 ; 1 = plain bf16 store ; 2 = gamma*acc + Xres -> fp32 ;
//      3 = +bias[col] -> bf16
template<int EPI>
__global__ __launch_bounds__(256, 2) void gemm_kernel(
    const bf16* __restrict__ A, size_t strideA, int ldA,
    const bf16* __restrict__ B, size_t strideB, int ldB,
    void* __restrict__ Cv, size_t strideC, int ldC,
    const float* __restrict__ bias,
    const float* __restrict__ Xres, const float* __restrict__ gammap,
    int K)
{
    __shared__ __align__(16) bf16 As[2][128 * 40];
    __shared__ __align__(16) bf16 Bs[2][128 * 40];

    int tid = threadIdx.x;
    int b   = blockIdx.z;
    int m0  = blockIdx.y * 128, n0 = blockIdx.x * 128;
    const bf16* Ab = A + strideA * b + (size_t)m0 * ldA;
    const bf16* Bb = B + strideB * b + (size_t)n0 * ldB;

    int w = tid >> 5, lane = tid & 31;
    int wm = w >> 2, wn = w & 3;          // 2 x 4 warps
    int g  = lane >> 2, tig = lane & 3;

    // ldmatrix per-lane addressing (quad = which 8x8 matrix, lr = row in it)
    int lq = lane >> 3, lr = lane & 7;
    // A x4: q0=(m0-7,k0-7) q1=(m8-15,k0-7) q2=(m0-7,k8-15) q3=(m8-15,k8-15)
    uint32_t a_row  = wm * 64 + ((lq & 1) << 3) + lr;     // + mf*16
    uint32_t a_koff = (lq >> 1) << 3;                      // + kb
    // B x4: q0=(nf,k0-7) q1=(nf,k8-15) q2=(nf+1,k0-7) q3=(nf+1,k8-15)
    uint32_t b_row  = wn * 32 + ((lq >> 1) << 3) + lr;     // + nfpair*16
    uint32_t b_koff = (lq & 1) << 3;                       // + kb

    uint32_t As_s = (uint32_t)__cvta_generic_to_shared(&As[0][0]);
    uint32_t Bs_s = (uint32_t)__cvta_generic_to_shared(&Bs[0][0]);
    const uint32_t BUF = 128 * 40 * 2;   // bytes per buffer

    float acc[4][4][4] = {};

    // prologue: tile 0 -> smem buffer 0
    uint4 ra[2], rb[2];
    load_tile_regs(ra, Ab, ldA, tid);
    load_tile_regs(rb, Bb, ldB, tid);
    store_tile_regs(As[0], ra, tid);
    store_tile_regs(Bs[0], rb, tid);
    __syncthreads();

    int ntiles = K >> 5;
    int cur = 0;
    for (int kt = 0; kt < ntiles; kt++) {
        if (kt + 1 < ntiles) {
            load_tile_regs(ra, Ab + ((kt + 1) << 5), ldA, tid);
            load_tile_regs(rb, Bb + ((kt + 1) << 5), ldB, tid);
        }

        uint32_t a_s = As_s + cur * BUF + (a_row * 40 + a_koff) * 2;
        uint32_t b_s = Bs_s + cur * BUF + (b_row * 40 + b_koff) * 2;

        #pragma unroll
        for (int ks = 0; ks < 2; ks++) {
            int kb2 = ks * 16 * 2;   // byte offset of k-step
            uint32_t af[4][4], bfr[8];
            #pragma unroll
            for (int mf = 0; mf < 4; mf++)
                ldsm_x4(af[mf], a_s + kb2 + mf * (16 * 40 * 2));
            ldsm_x4(bfr + 0, b_s + kb2);                    // nf 0,1
            ldsm_x4(bfr + 4, b_s + kb2 + 16 * 40 * 2);      // nf 2,3
            #pragma unroll
            for (int mf = 0; mf < 4; mf++)
                #pragma unroll
                for (int nf = 0; nf < 4; nf++)
                    mma16816(acc[mf][nf], af[mf], bfr + nf * 2);
        }

        if (kt + 1 < ntiles) {
            store_tile_regs(As[cur ^ 1], ra, tid);
            store_tile_regs(Bs[cur ^ 1], rb, tid);
            __syncthreads();
            cur ^= 1;
        }
    }

    float gv = (EPI == 2) ? *gammap : 0.f;

    #pragma unroll
    for (int mf = 0; mf < 4; mf++) {
        #pragma unroll
        for (int rr = 0; rr < 2; rr++) {
            int row = m0 + wm * 64 + mf * 16 + rr * 8 + g;
            #pragma unroll
            for (int nf = 0; nf < 4; nf++) {
                int col = n0 + wn * 32 + nf * 8 + 2 * tig;
                float d0 = acc[mf][nf][rr * 2 + 0];
                float d1 = acc[mf][nf][rr * 2 + 1];
                size_t idx = strideC * b + (size_t)row * ldC + col;
                if (EPI == 0) {
                    float bv = bias[row];
                    *(__nv_bfloat162*)((bf16*)Cv + idx) =
                        __float22bfloat162_rn(make_float2(d0 + bv, d1 + bv));
                } else if (EPI == 1) {
                    *(__nv_bfloat162*)((bf16*)Cv + idx) =
                        __float22bfloat162_rn(make_float2(d0, d1));
                } else if (EPI == 2) {
                    float2 xv = *(const float2*)(Xres + idx);
                    *(float2*)((float*)Cv + idx) =
                        make_float2(gv * d0 + xv.x, gv * d1 + xv.y);
                } else {
                    *(__nv_bfloat162*)((bf16*)Cv + idx) =
                        __float22bfloat162_rn(make_float2(d0 + bias[col], d1 + bias[col + 1]));
                }
            }
        }
    }
}

// ---------------- row softmax, in place on g_pb (bf16), 16B vectorized -----
__global__ __launch_bounds__(256) void softmax_kernel()
{
    __shared__ float red[8];
    size_t row = blockIdx.x;
    bf16* r = g_pb + row * (size_t)NPIX;
    int tid = threadIdx.x;

    uint4 pk[2];
    float v[16];
    float lmax = -1e30f;
    #pragma unroll
    for (int e = 0; e < 2; e++) {
        pk[e] = *(const uint4*)(r + 8 * (tid + 256 * e));
        const __nv_bfloat162* h2 = (const __nv_bfloat162*)&pk[e];
        #pragma unroll
        for (int q = 0; q < 4; q++) {
            float2 f2 = __bfloat1622float2(h2[q]);
            v[8 * e + 2 * q]     = f2.x;
            v[8 * e + 2 * q + 1] = f2.y;
            lmax = fmaxf(lmax, fmaxf(f2.x, f2.y));
        }
    }
    #pragma unroll
    for (int off = 16; off > 0; off >>= 1)
        lmax = fmaxf(lmax, __shfl_xor_sync(0xffffffffu, lmax, off));
    if ((tid & 31) == 0) red[tid >> 5] = lmax;
    __syncthreads();
    float m = red[0];
    #pragma unroll
    for (int i = 1; i < 8; i++) m = fmaxf(m, red[i]);
    __syncthreads();

    float lsum = 0.f;
    #pragma unroll
    for (int e = 0; e < 16; e++) {
        v[e] = __expf(v[e] - m);
        lsum += v[e];
    }
    #pragma unroll
    for (int off = 16; off > 0; off >>= 1)
        lsum += __shfl_xor_sync(0xffffffffu, lsum, off);
    if ((tid & 31) == 0) red[tid >> 5] = lsum;
    __syncthreads();
    float s = 0.f;
    #pragma unroll
    for (int i = 0; i < 8; i++) s += red[i];
    float inv = 1.0f / s;

    #pragma unroll
    for (int e = 0; e < 2; e++) {
        __nv_bfloat162* h2 = (__nv_bfloat162*)&pk[e];
        #pragma unroll
        for (int q = 0; q < 4; q++)
            h2[q] = __float22bfloat162_rn(
                make_float2(v[8 * e + 2 * q] * inv, v[8 * e + 2 * q + 1] * inv));
        *(uint4*)(r + 8 * (tid + 256 * e)) = pk[e];
    }
}

// ---------------------------------------------------------------------------
extern "C" void kernel_launch(void* const* d_in, const int* in_sizes, int n_in,
                              void* d_out, int out_size)
{
    const float* x     = (const float*)d_in[0];
    const float* f_w   = (const float*)d_in[1];
    const float* f_b   = (const float*)d_in[2];
    const float* g_w   = (const float*)d_in[3];
    const float* g_b   = (const float*)d_in[4];
    const float* h_w   = (const float*)d_in[5];
    const float* h_b   = (const float*)d_in[6];
    const float* gamma = (const float*)d_in[7];
    float* out = (float*)d_out;

    bf16 *xt, *wfg, *wh, *fg, *hv, *pb;
    float *bfg;
    cudaGetSymbolAddress((void**)&xt,  g_xt);
    cudaGetSymbolAddress((void**)&wfg, g_wfg);
    cudaGetSymbolAddress((void**)&wh,  g_wh);
    cudaGetSymbolAddress((void**)&fg,  g_fg);
    cudaGetSymbolAddress((void**)&hv,  g_hv);
    cudaGetSymbolAddress((void**)&pb,  g_pb);
    cudaGetSymbolAddress((void**)&bfg, g_bfg);

    // 0) weights -> bf16; x -> x^T bf16
    pack_kernel<<<(CDIM * CDIM) / 256, 256>>>(f_w, f_b, g_w, g_b, h_w);
    transpose_x<<<dim3(NPIX / 32, CDIM / 64, BATCH), dim3(32, 8)>>>(x);

    // 1) fgT[n, o] = sum_c xT[n,c] * wfg[o,c] + bias[o]   (M=4096, N=128, K=512) -> bf16
    gemm_kernel<3><<<dim3(1, NPIX / 128, BATCH), 256>>>(
        xt, (size_t)NPIX * CDIM, CDIM,
        wfg, 0, CDIM,
        fg, (size_t)NPIX * 128, 128,
        bfg, nullptr, nullptr, CDIM);

    // 2) h[c, n] = sum_k h_w[c,k] * xT[n,k] + h_b[c]      (M=512, N=4096, K=512) -> bf16
    gemm_kernel<0><<<dim3(NPIX / 128, CDIM / 128, BATCH), 256>>>(
        wh, 0, CDIM,
        xt, (size_t)NPIX * CDIM, CDIM,
        hv, (size_t)CDIM * NPIX, NPIX,
        h_b, nullptr, nullptr, CDIM);

    // 3) P[j, i] = sum_o gT[j,o] * fT[i,o]                (M=N=4096, K=64) -> bf16
    gemm_kernel<1><<<dim3(NPIX / 128, NPIX / 128, BATCH), 256>>>(
        fg + 64, (size_t)NPIX * 128, 128,
        fg,      (size_t)NPIX * 128, 128,
        pb, (size_t)NPIX * NPIX, NPIX,
        nullptr, nullptr, nullptr, ODIM);

    // 4) in-place row softmax over P rows (== softmax over dim=1 of original scores)
    softmax_kernel<<<BATCH * NPIX, 256>>>();

    // 5) out[c,m] = gamma * sum_n h[c,n] * Pb[m,n] + x[c,m]  (K=4096) -> fp32
    gemm_kernel<2><<<dim3(NPIX / 128, CDIM / 128, BATCH), 256>>>(
        hv, (size_t)CDIM * NPIX, NPIX,
        pb, (size_t)NPIX * NPIX, NPIX,
        out, (size_t)CDIM * NPIX, NPIX,
        nullptr, x, gamma, NPIX);
}

// round 15
// speedup vs baseline: 1.1614x; 1.0746x over previous
#include <cuda_runtime.h>
#include <cuda_bf16.h>
#include <cstdint>

#define BATCH 4
#define CDIM  512
#define NPIX  4096
#define ODIM  64

typedef __nv_bfloat16 bf16;

// ---------------- scratch (device globals; runtime alloc forbidden) --------
__device__ __align__(16) bf16  g_xt [BATCH * NPIX * CDIM];          // x^T bf16 [b][n][c]
__device__ __align__(16) bf16  g_wfg[128 * CDIM];                   // stacked f_w,g_w bf16
__device__ __align__(16) float g_bfg[128];                          // stacked f_b,g_b
__device__ __align__(16) bf16  g_wh [CDIM * CDIM];                  // h_w bf16
__device__ __align__(16) bf16  g_fg [BATCH * NPIX * 128];           // fgT[b][n][o]
__device__ __align__(16) bf16  g_hv [BATCH * CDIM * NPIX];          // h projection bf16 [b][c][n]
__device__ __align__(16) bf16  g_pb [(size_t)BATCH * NPIX * NPIX];  // scores^T -> probs, bf16 in place

// ---------------- weight pack -----------------------------------------------
__global__ void pack_kernel(const float* __restrict__ fw, const float* __restrict__ fb,
                            const float* __restrict__ gw, const float* __restrict__ gb,
                            const float* __restrict__ hw)
{
    int i = blockIdx.x * 256 + threadIdx.x;
    if (i < 128 * CDIM)
        g_wfg[i] = __float2bfloat16(i < 64 * CDIM ? fw[i] : gw[i - 64 * CDIM]);
    if (i < CDIM * CDIM)
        g_wh[i] = __float2bfloat16(hw[i]);
    if (i < 128)
        g_bfg[i] = (i < 64) ? fb[i] : gb[i - 64];
}

// ---------------- x transpose: [b][c][n] fp32 -> [b][n][c] bf16 -------------
__global__ __launch_bounds__(256) void transpose_x(const float* __restrict__ x)
{
    __shared__ float t[64][33];
    int b  = blockIdx.z;
    int c0 = blockIdx.y * 64;
    int n0 = blockIdx.x * 32;
    const float* xb = x + (size_t)b * CDIM * NPIX;
    bf16* xo = g_xt + (size_t)b * NPIX * CDIM;
    int tx = threadIdx.x, ty = threadIdx.y;

    #pragma unroll
    for (int e = 0; e < 8; e++) {
        int c = 8 * e + ty;
        t[c][tx] = xb[(size_t)(c0 + c) * NPIX + n0 + tx];
    }
    __syncthreads();
    #pragma unroll
    for (int e = 0; e < 4; e++) {
        int n = ty + 8 * e;
        __nv_bfloat162 v = __float22bfloat162_rn(
            make_float2(t[2 * tx][n], t[2 * tx + 1][n]));
        *(__nv_bfloat162*)(xo + (size_t)(n0 + n) * CDIM + c0 + 2 * tx) = v;
    }
}

// ---------------- mma / ldmatrix helpers ------------------------------------
__device__ __forceinline__ void mma16816(float* d, const uint32_t* a, const uint32_t* b)
{
    asm volatile(
        "mma.sync.aligned.m16n8k16.row.col.f32.bf16.bf16.f32 "
        "{%0,%1,%2,%3}, {%4,%5,%6,%7}, {%8,%9}, {%0,%1,%2,%3};"
        : "+f"(d[0]), "+f"(d[1]), "+f"(d[2]), "+f"(d[3])
        : "r"(a[0]), "r"(a[1]), "r"(a[2]), "r"(a[3]), "r"(b[0]), "r"(b[1]));
}

__device__ __forceinline__ void ldsm_x4(uint32_t* r, uint32_t saddr)
{
    asm volatile("ldmatrix.sync.aligned.m8n8.x4.shared.b16 {%0,%1,%2,%3}, [%4];"
        : "=r"(r[0]), "=r"(r[1]), "=r"(r[2]), "=r"(r[3]) : "r"(saddr));
}

// ---------------- tile staging (128 threads, 128 rows x 32 k halfs) --------
__device__ __forceinline__ void load_tile_regs(uint4* r, const bf16* src, int ld, int tid)
{
    #pragma unroll
    for (int e = 0; e < 4; e++) {
        int c = tid + 128 * e;           // 512 chunks of 8 halfs
        int rr = c >> 2, q = c & 3;
        r[e] = *(const uint4*)(src + (size_t)rr * ld + 8 * q);
    }
}
__device__ __forceinline__ void store_tile_regs(bf16* sm, const uint4* r, int tid)
{
    #pragma unroll
    for (int e = 0; e < 4; e++) {
        int c = tid + 128 * e;
        int rr = c >> 2, q = c & 3;
        *(uint4*)(sm + rr * 40 + 8 * q) = r[e];   // row stride 40: conflict-free
    }
}

// ---------------- unified bf16 GEMM -----------------------------------------
// Block 128x128, 4 warps (2x2), warp tile 64x64, Ktile 32, double-buffered.
// C[m,n] = sum_k A[m,k] * B[n,k]  (fp32 accum).
// EPI: 0 = +bias[row] -> bf16 ; 1 = plain bf16 store ; 2 = gamma*acc + Xres -> fp32 ;
//      3 = +bias[col] -> bf16
template<int EPI>
__global__ __launch_bounds__(128, 2) void gemm_kernel(
    const bf16* __restrict__ A, size_t strideA, int ldA,
    const bf16* __restrict__ B, size_t strideB, int ldB,
    void* __restrict__ Cv, size_t strideC, int ldC,
    const float* __restrict__ bias,
    const float* __restrict__ Xres, const float* __restrict__ gammap,
    int K)
{
    __shared__ __align__(16) bf16 As[2][128 * 40];
    __shared__ __align__(16) bf16 Bs[2][128 * 40];

    int tid = threadIdx.x;
    int b   = blockIdx.z;
    int m0  = blockIdx.y * 128, n0 = blockIdx.x * 128;
    const bf16* Ab = A + strideA * b + (size_t)m0 * ldA;
    const bf16* Bb = B + strideB * b + (size_t)n0 * ldB;

    int w = tid >> 5, lane = tid & 31;
    int wm = w >> 1, wn = w & 1;          // 2 x 2 warps, 64x64 tiles
    int g  = lane >> 2, tig = lane & 3;

    // ldmatrix per-lane addressing
    int lq = lane >> 3, lr = lane & 7;
    // A x4: q0=(m0-7,k0-7) q1=(m8-15,k0-7) q2=(m0-7,k8-15) q3=(m8-15,k8-15)
    uint32_t a_row  = wm * 64 + ((lq & 1) << 3) + lr;     // + mf*16
    uint32_t a_koff = (lq >> 1) << 3;
    // B x4: q0=(nf,k0-7) q1=(nf,k8-15) q2=(nf+1,k0-7) q3=(nf+1,k8-15)
    uint32_t b_row  = wn * 64 + ((lq >> 1) << 3) + lr;    // + nfpair*16
    uint32_t b_koff = (lq & 1) << 3;

    uint32_t As_s = (uint32_t)__cvta_generic_to_shared(&As[0][0]);
    uint32_t Bs_s = (uint32_t)__cvta_generic_to_shared(&Bs[0][0]);
    const uint32_t BUF = 128 * 40 * 2;

    float acc[4][8][4] = {};

    uint4 ra[4], rb[4];
    load_tile_regs(ra, Ab, ldA, tid);
    load_tile_regs(rb, Bb, ldB, tid);
    store_tile_regs(As[0], ra, tid);
    store_tile_regs(Bs[0], rb, tid);
    __syncthreads();

    int ntiles = K >> 5;
    int cur = 0;
    for (int kt = 0; kt < ntiles; kt++) {
        if (kt + 1 < ntiles) {
            load_tile_regs(ra, Ab + ((kt + 1) << 5), ldA, tid);
            load_tile_regs(rb, Bb + ((kt + 1) << 5), ldB, tid);
        }

        uint32_t a_s = As_s + cur * BUF + (a_row * 40 + a_koff) * 2;
        uint32_t b_s = Bs_s + cur * BUF + (b_row * 40 + b_koff) * 2;

        #pragma unroll
        for (int ks = 0; ks < 2; ks++) {
            int kb2 = ks * 16 * 2;
            uint32_t af[4][4], bfr[16];
            #pragma unroll
            for (int mf = 0; mf < 4; mf++)
                ldsm_x4(af[mf], a_s + kb2 + mf * (16 * 40 * 2));
            #pragma unroll
            for (int j = 0; j < 4; j++)
                ldsm_x4(bfr + 4 * j, b_s + kb2 + j * (16 * 40 * 2));  // nf 2j,2j+1
            #pragma unroll
            for (int mf = 0; mf < 4; mf++)
                #pragma unroll
                for (int nf = 0; nf < 8; nf++)
                    mma16816(acc[mf][nf], af[mf], bfr + nf * 2);
        }

        if (kt + 1 < ntiles) {
            store_tile_regs(As[cur ^ 1], ra, tid);
            store_tile_regs(Bs[cur ^ 1], rb, tid);
            __syncthreads();
            cur ^= 1;
        }
    }

    float gv = (EPI == 2) ? *gammap : 0.f;

    #pragma unroll
    for (int mf = 0; mf < 4; mf++) {
        #pragma unroll
        for (int rr = 0; rr < 2; rr++) {
            int row = m0 + wm * 64 + mf * 16 + rr * 8 + g;
            #pragma unroll
            for (int nf = 0; nf < 8; nf++) {
                int col = n0 + wn * 64 + nf * 8 + 2 * tig;
                float d0 = acc[mf][nf][rr * 2 + 0];
                float d1 = acc[mf][nf][rr * 2 + 1];
                size_t idx = strideC * b + (size_t)row * ldC + col;
                if (EPI == 0) {
                    float bv = bias[row];
                    *(__nv_bfloat162*)((bf16*)Cv + idx) =
                        __float22bfloat162_rn(make_float2(d0 + bv, d1 + bv));
                } else if (EPI == 1) {
                    *(__nv_bfloat162*)((bf16*)Cv + idx) =
                        __float22bfloat162_rn(make_float2(d0, d1));
                } else if (EPI == 2) {
                    float2 xv = *(const float2*)(Xres + idx);
                    *(float2*)((float*)Cv + idx) =
                        make_float2(gv * d0 + xv.x, gv * d1 + xv.y);
                } else {
                    *(__nv_bfloat162*)((bf16*)Cv + idx) =
                        __float22bfloat162_rn(make_float2(d0 + bias[col], d1 + bias[col + 1]));
                }
            }
        }
    }
}

// ---------------- row softmax, in place on g_pb (bf16), 16B vectorized -----
__global__ __launch_bounds__(256) void softmax_kernel()
{
    __shared__ float red[8];
    size_t row = blockIdx.x;
    bf16* r = g_pb + row * (size_t)NPIX;
    int tid = threadIdx.x;

    uint4 pk[2];
    float v[16];
    float lmax = -1e30f;
    #pragma unroll
    for (int e = 0; e < 2; e++) {
        pk[e] = *(const uint4*)(r + 8 * (tid + 256 * e));
        const __nv_bfloat162* h2 = (const __nv_bfloat162*)&pk[e];
        #pragma unroll
        for (int q = 0; q < 4; q++) {
            float2 f2 = __bfloat1622float2(h2[q]);
            v[8 * e + 2 * q]     = f2.x;
            v[8 * e + 2 * q + 1] = f2.y;
            lmax = fmaxf(lmax, fmaxf(f2.x, f2.y));
        }
    }
    #pragma unroll
    for (int off = 16; off > 0; off >>= 1)
        lmax = fmaxf(lmax, __shfl_xor_sync(0xffffffffu, lmax, off));
    if ((tid & 31) == 0) red[tid >> 5] = lmax;
    __syncthreads();
    float m = red[0];
    #pragma unroll
    for (int i = 1; i < 8; i++) m = fmaxf(m, red[i]);
    __syncthreads();

    float lsum = 0.f;
    #pragma unroll
    for (int e = 0; e < 16; e++) {
        v[e] = __expf(v[e] - m);
        lsum += v[e];
    }
    #pragma unroll
    for (int off = 16; off > 0; off >>= 1)
        lsum += __shfl_xor_sync(0xffffffffu, lsum, off);
    if ((tid & 31) == 0) red[tid >> 5] = lsum;
    __syncthreads();
    float s = 0.f;
    #pragma unroll
    for (int i = 0; i < 8; i++) s += red[i];
    float inv = 1.0f / s;

    #pragma unroll
    for (int e = 0; e < 2; e++) {
        __nv_bfloat162* h2 = (__nv_bfloat162*)&pk[e];
        #pragma unroll
        for (int q = 0; q < 4; q++)
            h2[q] = __float22bfloat162_rn(
                make_float2(v[8 * e + 2 * q] * inv, v[8 * e + 2 * q + 1] * inv));
        *(uint4*)(r + 8 * (tid + 256 * e)) = pk[e];
    }
}

// ---------------------------------------------------------------------------
extern "C" void kernel_launch(void* const* d_in, const int* in_sizes, int n_in,
                              void* d_out, int out_size)
{
    const float* x     = (const float*)d_in[0];
    const float* f_w   = (const float*)d_in[1];
    const float* f_b   = (const float*)d_in[2];
    const float* g_w   = (const float*)d_in[3];
    const float* g_b   = (const float*)d_in[4];
    const float* h_w   = (const float*)d_in[5];
    const float* h_b   = (const float*)d_in[6];
    const float* gamma = (const float*)d_in[7];
    float* out = (float*)d_out;

    bf16 *xt, *wfg, *wh, *fg, *hv, *pb;
    float *bfg;
    cudaGetSymbolAddress((void**)&xt,  g_xt);
    cudaGetSymbolAddress((void**)&wfg, g_wfg);
    cudaGetSymbolAddress((void**)&wh,  g_wh);
    cudaGetSymbolAddress((void**)&fg,  g_fg);
    cudaGetSymbolAddress((void**)&hv,  g_hv);
    cudaGetSymbolAddress((void**)&pb,  g_pb);
    cudaGetSymbolAddress((void**)&bfg, g_bfg);

    // 0) weights -> bf16; x -> x^T bf16
    pack_kernel<<<(CDIM * CDIM) / 256, 256>>>(f_w, f_b, g_w, g_b, h_w);
    transpose_x<<<dim3(NPIX / 32, CDIM / 64, BATCH), dim3(32, 8)>>>(x);

    // 1) fgT[n, o] = sum_c xT[n,c] * wfg[o,c] + bias[o]   (M=4096, N=128, K=512) -> bf16
    gemm_kernel<3><<<dim3(1, NPIX / 128, BATCH), 128>>>(
        xt, (size_t)NPIX * CDIM, CDIM,
        wfg, 0, CDIM,
        fg, (size_t)NPIX * 128, 128,
        bfg, nullptr, nullptr, CDIM);

    // 2) h[c, n] = sum_k h_w[c,k] * xT[n,k] + h_b[c]      (M=512, N=4096, K=512) -> bf16
    gemm_kernel<0><<<dim3(NPIX / 128, CDIM / 128, BATCH), 128>>>(
        wh, 0, CDIM,
        xt, (size_t)NPIX * CDIM, CDIM,
        hv, (size_t)CDIM * NPIX, NPIX,
        h_b, nullptr, nullptr, CDIM);

    // 3) P[j, i] = sum_o gT[j,o] * fT[i,o]                (M=N=4096, K=64) -> bf16
    gemm_kernel<1><<<dim3(NPIX / 128, NPIX / 128, BATCH), 128>>>(
        fg + 64, (size_t)NPIX * 128, 128,
        fg,      (size_t)NPIX * 128, 128,
        pb, (size_t)NPIX * NPIX, NPIX,
        nullptr, nullptr, nullptr, ODIM);

    // 4) in-place row softmax over P rows (== softmax over dim=1 of original scores)
    softmax_kernel<<<BATCH * NPIX, 256>>>();

    // 5) out[c,m] = gamma * sum_n h[c,n] * Pb[m,n] + x[c,m]  (K=4096) -> fp32
    gemm_kernel<2><<<dim3(NPIX / 128, CDIM / 128, BATCH), 128>>>(
        hv, (size_t)CDIM * NPIX, NPIX,
        pb, (size_t)NPIX * NPIX, NPIX,
        out, (size_t)CDIM * NPIX, NPIX,
        nullptr, x, gamma, NPIX);
}